// round 9
// baseline (speedup 1.0000x reference)
#include <cuda_runtime.h>
#include <cuda_pipeline.h>
#include <cstdint>

// OptFP_Embedding: out[b,f,:] = beta + sum_i c_i(g) * clip(rint((W[x]-beta)*ia_i), lo_i, hi_i)
//   c_i = softmax(gamma)_i * (|alpha_i|+eps); sum_i softmax = 1 folds beta out.
//
// Strategy: CONTINUOUS ROLLING PIPELINE (issue-duty-cycle fix).
//   Single resident wave (740 blocks = 148 SMs x 5), grid-stride loop.
//   Per thread: 4-stage cp.async ring for row payloads, 8-deep register ring
//   for x-indices, 4-deep for groups. Every dependent load is issued 4-8
//   iterations before its use (>=2900 cyc slack vs ~600 cyc DRAM), so compute
//   of iteration t overlaps loads of t+4..t+8 continuously instead of the
//   front-load/drain phase-bunching that capped issue at ~45%.
//
// Inputs (metadata order):
//   d_in[0] = x           int32   [4096*39]
//   d_in[1] = weight      float32 [1000000*64]
//   d_in[2] = group_index int32   [1000000]
//   d_in[3] = gamma       float32 [8*1*3]
//   d_in[4] = alpha       float32 [3]
//   d_in[5] = beta        float32 [64]
// Output: float32 [4096*39*64]

#define EMB_DIM 64
#define GROUPS 8
#define NBITS 3
#define TPT 16                    // threads per token (16 x float4 = 64 floats)
#define BLOCK_THREADS 256
#define SUBS (BLOCK_THREADS / TPT)   // 16 tokens in flight per block per iteration
#define BUF 4                        // cp.async ring depth (power of 2)
#define IDXD 8                       // index-register ring depth (power of 2)
#define GRID_BLOCKS 740              // 148 SMs x 5 resident blocks: one wave

__global__ __launch_bounds__(BLOCK_THREADS, 5)
void optfp_embedding_kernel(const int* __restrict__ x,
                            const float* __restrict__ weight,
                            const int* __restrict__ group_index,
                            const float* __restrict__ gamma,
                            const float* __restrict__ alpha,
                            const float* __restrict__ beta,
                            float* __restrict__ out,
                            int ntok) {
    __shared__ float4 s_rows[BUF][BLOCK_THREADS];   // 16 KB ring
    __shared__ float s_beta[EMB_DIM];
    __shared__ float s_c[GROUPS][NBITS];    // softmax(gamma)_i * (|alpha_i|+eps)
    __shared__ float s_ia[NBITS];           // 1 / (|alpha_i| + eps)

    const int tid = threadIdx.x;

    // ---- one-time coefficient tables ----
    if (tid < EMB_DIM) s_beta[tid] = beta[tid];
    if (tid < GROUPS) {
        // TAU = 1.0
        float g0 = gamma[tid * NBITS + 0];
        float g1 = gamma[tid * NBITS + 1];
        float g2 = gamma[tid * NBITS + 2];
        float m = fmaxf(g0, fmaxf(g1, g2));
        float e0 = __expf(g0 - m);
        float e1 = __expf(g1 - m);
        float e2 = __expf(g2 - m);
        float inv = 1.0f / (e0 + e1 + e2);
        s_c[tid][0] = e0 * inv * (fabsf(alpha[0]) + 1e-10f);
        s_c[tid][1] = e1 * inv * (fabsf(alpha[1]) + 1e-10f);
        s_c[tid][2] = e2 * inv * (fabsf(alpha[2]) + 1e-10f);
        if (tid == 0) {
            s_ia[0] = 1.0f / (fabsf(alpha[0]) + 1e-10f);
            s_ia[1] = 1.0f / (fabsf(alpha[1]) + 1e-10f);
            s_ia[2] = 1.0f / (fabsf(alpha[2]) + 1e-10f);
        }
    }

    const int sub  = tid >> 4;            // 0..15 : token slot within block
    const int lane = tid & (TPT - 1);     // 0..15 : 16B chunk within a row

    const unsigned S = (unsigned)gridDim.x * SUBS;      // token stride per iteration
    unsigned tokc = (unsigned)blockIdx.x * SUBS + sub;  // compute token, iter 0
    const unsigned blk0 = (unsigned)blockIdx.x * SUBS;
    const int niter = (blk0 < (unsigned)ntok)
                        ? (int)(((unsigned)ntok - blk0 + S - 1) / S) : 0;

    // ---- pipeline prologue ----
    int idxr[IDXD];   // idx for iterations t..t+7 (ring slot = iter & 7)
    int gr[BUF];      // group for iterations t..t+3 (ring slot = iter & 3)
#pragma unroll
    for (int k = 0; k < IDXD; k++) {
        const unsigned tk = tokc + (unsigned)k * S;
        idxr[k] = (tk < (unsigned)ntok) ? __ldg(x + tk) : 0;
    }
#pragma unroll
    for (int k = 0; k < BUF; k++)
        gr[k] = __ldg(group_index + idxr[k]);
#pragma unroll
    for (int k = 0; k < BUF; k++) {
        __pipeline_memcpy_async(&s_rows[k][tid],
                                (const float4*)weight + (((unsigned)idxr[k]) << 4) + lane,
                                sizeof(float4));
        __pipeline_commit();
    }

    __syncthreads();   // tables visible (prologue loads don't touch tables)

    const float4 b4 = ((const float4*)s_beta)[lane];
    const float ia0 = s_ia[0], ia1 = s_ia[1], ia2 = s_ia[2];

    unsigned tok_x   = tokc + (unsigned)IDXD * S;   // x prefetch cursor (iter t+8)
    unsigned out_i   = tokc * TPT + lane;           // float4 output index
    const unsigned out_step = S * TPT;

    // ---- steady-state rolling loop ----
    for (int t = 0; t < niter; ++t) {
        const int stage = t & (BUF - 1);

        // fire x load for iteration t+IDXD (consumed 8 iterations later)
        int newidx = 0;
        if (tok_x < (unsigned)ntok) newidx = __ldg(x + tok_x);
        tok_x += S;

        // wait for this iteration's row payload (issued BUF iterations ago)
        __pipeline_wait_prior(BUF - 1);
        const float4 w = s_rows[stage][tid];
        const int g = gr[stage];

        // refill the just-consumed stage for iteration t+BUF.
        // idx(t+BUF) was loaded IDXD-BUF=4 iterations ago -> no dependent stall.
        {
            const int idn = idxr[(t + BUF) & (IDXD - 1)];
            gr[stage] = __ldg(group_index + idn);
            __pipeline_memcpy_async(&s_rows[stage][tid],
                                    (const float4*)weight + (((unsigned)idn) << 4) + lane,
                                    sizeof(float4));
            __pipeline_commit();
        }
        idxr[t & (IDXD - 1)] = newidx;   // slot now holds idx for iter t+IDXD

        if (tokc < (unsigned)ntok) {
            const float c0 = s_c[g][0];
            const float c1 = s_c[g][1];
            const float c2 = s_c[g][2];

            const float wv[4] = {w.x, w.y, w.z, w.w};
            const float bv[4] = {b4.x, b4.y, b4.z, b4.w};
            float rv[4];
#pragma unroll
            for (int c = 0; c < 4; c++) {
                const float wb = wv[c] - bv[c];
                const float r0 = fminf(fmaxf(rintf(wb * ia0),   -2.0f),   1.0f);
                const float r1 = fminf(fmaxf(rintf(wb * ia1),   -8.0f),   7.0f);
                const float r2 = fminf(fmaxf(rintf(wb * ia2), -128.0f), 127.0f);
                float acc = fmaf(c0, r0, bv[c]);
                acc = fmaf(c1, r1, acc);
                rv[c] = fmaf(c2, r2, acc);
            }
            float4 r; r.x = rv[0]; r.y = rv[1]; r.z = rv[2]; r.w = rv[3];
            __stcs((float4*)out + out_i, r);
        }
        tokc += S;
        out_i += out_step;
    }
}

extern "C" void kernel_launch(void* const* d_in, const int* in_sizes, int n_in,
                              void* d_out, int out_size) {
    const int*   x           = (const int*)d_in[0];
    const float* weight      = (const float*)d_in[1];
    const int*   group_index = (const int*)d_in[2];
    const float* gamma       = (const float*)d_in[3];
    const float* alpha       = (const float*)d_in[4];
    const float* beta        = (const float*)d_in[5];
    float* out = (float*)d_out;

    const int ntok = in_sizes[0];  // 4096 * 39 = 159744
    int blocks = (ntok + SUBS - 1) / SUBS;
    if (blocks > GRID_BLOCKS) blocks = GRID_BLOCKS;
    optfp_embedding_kernel<<<blocks, BLOCK_THREADS>>>(
        x, weight, group_index, gamma, alpha, beta, out, ntok);
}

// round 10
// speedup vs baseline: 2.1152x; 2.1152x over previous
#include <cuda_runtime.h>
#include <cuda_pipeline.h>
#include <cstdint>

// OptFP_Embedding: out[b,f,:] = beta + sum_i c_i(g) * clip(rint((W[x]-beta)*ia_i), lo_i, hi_i)
//   c_i = softmax(gamma)_i * (|alpha_i|+eps); sum_i softmax = 1 folds beta out.
//
// Strategy: R5 cp.async self-staging structure, tuned for occupancy:
//   STAGES 8->6  (smem 33KB -> 24.6KB)
//   __launch_bounds__(256,7) caps regs at 36  -> 7 blocks/SM = 87.5% occupancy
//   group ids packed into one register (4-bit fields) to relieve reg pressure.
//   159744 = 96 * 1664 exactly -> guards never fire.
//
// Inputs (metadata order):
//   d_in[0] = x           int32   [4096*39]
//   d_in[1] = weight      float32 [1000000*64]
//   d_in[2] = group_index int32   [1000000]
//   d_in[3] = gamma       float32 [8*1*3]
//   d_in[4] = alpha       float32 [3]
//   d_in[5] = beta        float32 [64]
// Output: float32 [4096*39*64]

#define EMB_DIM 64
#define GROUPS 8
#define NBITS 3
#define TPT 16                    // threads per token (16 x float4 = 64 floats)
#define BLOCK_THREADS 256
#define SUBS (BLOCK_THREADS / TPT)        // 16 tokens per stage
#define STAGES 6                          // cp.async pipeline depth
#define TOKENS_PER_BLOCK (SUBS * STAGES)  // 96

__global__ __launch_bounds__(BLOCK_THREADS, 7)
void optfp_embedding_kernel(const int* __restrict__ x,
                            const float* __restrict__ weight,
                            const int* __restrict__ group_index,
                            const float* __restrict__ gamma,
                            const float* __restrict__ alpha,
                            const float* __restrict__ beta,
                            float* __restrict__ out,
                            int ntok) {
    __shared__ float4 s_rows[STAGES][BLOCK_THREADS];   // 24 KB staging
    __shared__ float s_beta[EMB_DIM];
    __shared__ float s_c[GROUPS][NBITS];    // softmax(gamma)_i * (|alpha_i|+eps)
    __shared__ float s_ia[NBITS];           // 1 / (|alpha_i| + eps)

    const int tid = threadIdx.x;

    // ---- one-time coefficient tables ----
    if (tid < EMB_DIM) s_beta[tid] = beta[tid];
    if (tid < GROUPS) {
        // TAU = 1.0
        float g0 = gamma[tid * NBITS + 0];
        float g1 = gamma[tid * NBITS + 1];
        float g2 = gamma[tid * NBITS + 2];
        float m = fmaxf(g0, fmaxf(g1, g2));
        float e0 = __expf(g0 - m);
        float e1 = __expf(g1 - m);
        float e2 = __expf(g2 - m);
        float inv = 1.0f / (e0 + e1 + e2);
        s_c[tid][0] = e0 * inv * (fabsf(alpha[0]) + 1e-10f);
        s_c[tid][1] = e1 * inv * (fabsf(alpha[1]) + 1e-10f);
        s_c[tid][2] = e2 * inv * (fabsf(alpha[2]) + 1e-10f);
        if (tid == 0) {
            s_ia[0] = 1.0f / (fabsf(alpha[0]) + 1e-10f);
            s_ia[1] = 1.0f / (fabsf(alpha[1]) + 1e-10f);
            s_ia[2] = 1.0f / (fabsf(alpha[2]) + 1e-10f);
        }
    }

    const int sub  = tid >> 4;            // 0..15 : token slot within a stage
    const int lane = tid & (TPT - 1);     // 0..15 : 16B chunk within a row

    const unsigned base = (unsigned)blockIdx.x * TOKENS_PER_BLOCK + sub;

    // ---- prologue: front-batched index gathers ----
    int idx[STAGES];
#pragma unroll
    for (int s = 0; s < STAGES; s++) {
        const unsigned tok = base + (unsigned)s * SUBS;
        idx[s] = (tok < (unsigned)ntok) ? __ldg(x + tok) : 0;
    }

    // group ids: 6 gathers packed into one register (4-bit fields)
    unsigned gpack = 0;
#pragma unroll
    for (int s = 0; s < STAGES; s++)
        gpack |= ((unsigned)__ldg(group_index + idx[s])) << (s * 4);

    // Table visibility barrier BEFORE staging traffic starts.
    __syncthreads();

    // ---- issue depth-6 cp.async row gathers (16B per thread per stage) ----
#pragma unroll
    for (int s = 0; s < STAGES; s++) {
        __pipeline_memcpy_async(&s_rows[s][tid],
                                (const float4*)weight + (((unsigned)idx[s]) << 4) + lane,
                                sizeof(float4));
        __pipeline_commit();
    }

    const float4 b4 = ((const float4*)s_beta)[lane];
    const float ia0 = s_ia[0], ia1 = s_ia[1], ia2 = s_ia[2];

    // ---- drain pipeline: compute one stage as each copy lands ----
#pragma unroll
    for (int s = 0; s < STAGES; s++) {
        __pipeline_wait_prior(STAGES - 1 - s);
        const unsigned tok = base + (unsigned)s * SUBS;
        if (tok >= (unsigned)ntok) continue;

        const float4 w = s_rows[s][tid];
        const int g = (gpack >> (s * 4)) & 7;
        const float c0 = s_c[g][0];
        const float c1 = s_c[g][1];
        const float c2 = s_c[g][2];

        const float wv[4] = {w.x, w.y, w.z, w.w};
        const float bv[4] = {b4.x, b4.y, b4.z, b4.w};
        float rv[4];
#pragma unroll
        for (int c = 0; c < 4; c++) {
            const float wb = wv[c] - bv[c];
            const float r0 = fminf(fmaxf(rintf(wb * ia0),   -2.0f),   1.0f);
            const float r1 = fminf(fmaxf(rintf(wb * ia1),   -8.0f),   7.0f);
            const float r2 = fminf(fmaxf(rintf(wb * ia2), -128.0f), 127.0f);
            float acc = fmaf(c0, r0, bv[c]);
            acc = fmaf(c1, r1, acc);
            rv[c] = fmaf(c2, r2, acc);
        }
        float4 r; r.x = rv[0]; r.y = rv[1]; r.z = rv[2]; r.w = rv[3];
        __stcs((float4*)out + tok * TPT + lane, r);
    }
}

extern "C" void kernel_launch(void* const* d_in, const int* in_sizes, int n_in,
                              void* d_out, int out_size) {
    const int*   x           = (const int*)d_in[0];
    const float* weight      = (const float*)d_in[1];
    const int*   group_index = (const int*)d_in[2];
    const float* gamma       = (const float*)d_in[3];
    const float* alpha       = (const float*)d_in[4];
    const float* beta        = (const float*)d_in[5];
    float* out = (float*)d_out;

    const int ntok = in_sizes[0];  // 4096 * 39 = 159744 = 96 * 1664
    const int blocks = (ntok + TOKENS_PER_BLOCK - 1) / TOKENS_PER_BLOCK;
    optfp_embedding_kernel<<<blocks, BLOCK_THREADS>>>(
        x, weight, group_index, gamma, alpha, beta, out, ntok);
}